// round 9
// baseline (speedup 1.0000x reference)
#include <cuda_runtime.h>
#include <cuda_bf16.h>
#include <cstdint>

// out[b,s] = | prod_k cos((x[b,k]-sv[s,k])/2) |  =  | P12 * P34 |
// P12 = 1/2 [ cos((u+ - v+)/2) + cos((u- - v-)/2) ],  u± = x0±x1, v± = s0±s1
// each cos((u-v)/2) = cos(u/2)cos(v/2) + sin(u/2)sin(v/2)
// -> each P is a 4-term dot product of row features vs col features (1/2
//    folded into the row side).
#define NB 4096
#define NS 4096

__device__ __forceinline__ uint64_t mul2(uint64_t a, uint64_t b) {
    uint64_t r; asm("mul.rn.f32x2 %0, %1, %2;" : "=l"(r) : "l"(a), "l"(b)); return r;
}
__device__ __forceinline__ uint64_t fma2(uint64_t a, uint64_t b, uint64_t c) {
    uint64_t r; asm("fma.rn.f32x2 %0, %1, %2, %3;" : "=l"(r) : "l"(a), "l"(b), "l"(c)); return r;
}
__device__ __forceinline__ uint64_t abs2(uint64_t v) {
    asm("and.b64 %0, %0, 0x7FFFFFFF7FFFFFFF;" : "+l"(v)); return v;
}
__device__ __forceinline__ uint64_t dup2(float v) {
    uint64_t r; asm("mov.b64 %0, {%1, %1};" : "=l"(r) : "f"(v)); return r;
}
// streaming 16B store, evict-first (output is write-once, never re-read)
__device__ __forceinline__ void stg_cs_128(float* p, uint64_t lo, uint64_t hi) {
    asm volatile("st.global.cs.v2.u64 [%0], {%1, %2};"
                 :: "l"(p), "l"(lo), "l"(hi) : "memory");
}

// Block: 64 rows x 256 cols. Thread: 4 cols x 16 rows.
// launch_bounds(256,5): cap regs at 51 -> 5 blocks/SM (40 warps, 62.5% occ).
__global__ __launch_bounds__(256, 5) void qk_pair_kernel(
    const float* __restrict__ x,
    const float* __restrict__ sv,
    float* __restrict__ out)
{
    // A (row) features: per row 16 floats = 4 groups of (c,c,s,s) pre-dup'd.
    __shared__ __align__(16) float sxf[64 * 16];   // 4 KB
    // B (col) features f-major: {C+12,S+12,C-12,S-12,C+34,S+34,C-34,S-34}
    __shared__ __align__(16) float sbf[8 * 256];   // 8 KB

    const int b0 = blockIdx.y << 6;    // 64 rows
    const int s0 = blockIdx.x << 8;    // 256 cols
    const int t  = threadIdx.x;

    // ---- A fill: one sincos/thread (t = row*4 + g) ----
    {
        const int g = t & 3;
        float v = x[b0 * 4 + t];                       // coalesced
        float p = __shfl_xor_sync(0xFFFFFFFFu, v, 1);  // pair partner
        float u = (g & 1) ? (p - v) : (v + p);
        float sn, cs;
        __sincosf(u * 0.5f, &sn, &cs);
        cs *= 0.5f; sn *= 0.5f;                        // fold the 1/2 per pair
        uint64_t* rec = reinterpret_cast<uint64_t*>(sxf) + ((t >> 2) << 3) + (g << 1);
        rec[0] = dup2(cs);
        rec[1] = dup2(sn);
    }
    // ---- B fill: one col per thread, 4 sincos ----
    {
        float4 v = *reinterpret_cast<const float4*>(&sv[(size_t)(s0 + t) * 4]);
        float sn, cs;
        __sincosf((v.x + v.y) * 0.5f, &sn, &cs); sbf[0*256 + t] = cs; sbf[1*256 + t] = sn;
        __sincosf((v.x - v.y) * 0.5f, &sn, &cs); sbf[2*256 + t] = cs; sbf[3*256 + t] = sn;
        __sincosf((v.z + v.w) * 0.5f, &sn, &cs); sbf[4*256 + t] = cs; sbf[5*256 + t] = sn;
        __sincosf((v.z - v.w) * 0.5f, &sn, &cs); sbf[6*256 + t] = cs; sbf[7*256 + t] = sn;
    }
    __syncthreads();

    const int cg = t & 63;   // 4 cols starting at s0 + 4*cg
    const int rg = t >> 6;   // 16 rows starting at b0 + 16*rg (warp-uniform)

    // ---- hoist B features: 8 coalesced LDS.128 (32 regs, persistent) ----
    ulonglong2 B[8];
#pragma unroll
    for (int f = 0; f < 8; f++)
        B[f] = *reinterpret_cast<const ulonglong2*>(&sbf[f * 256 + (cg << 2)]);

    float* orow = out + (size_t)(b0 + (rg << 4)) * NS + (s0 + (cg << 2));

#pragma unroll 4
    for (int i = 0; i < 16; i++) {
        const ulonglong2* arec = reinterpret_cast<const ulonglong2*>(
            &sxf[(((rg << 4) + i) << 4)]);          // warp-broadcast loads

        // First half of the A record: the "12" pair features.
        ulonglong2 q0 = arec[0];   // {c+12 dup, s+12 dup}
        ulonglong2 q1 = arec[1];   // {c-12 dup, s-12 dup}
        // balanced 2+2 trees (dep depth 3) for both column pairs
        uint64_t p12a = fma2(q1.y, B[3].x, fma2(q1.x, B[2].x,
                        fma2(q0.y, B[1].x, mul2(q0.x, B[0].x))));
        uint64_t p12b = fma2(q1.y, B[3].y, fma2(q1.x, B[2].y,
                        fma2(q0.y, B[1].y, mul2(q0.x, B[0].y))));

        // Second half: the "34" pair features (reuses q registers).
        q0 = arec[2];              // {c+34 dup, s+34 dup}
        q1 = arec[3];              // {c-34 dup, s-34 dup}
        uint64_t p34a = fma2(q1.y, B[7].x, fma2(q1.x, B[6].x,
                        fma2(q0.y, B[5].x, mul2(q0.x, B[4].x))));
        uint64_t p34b = fma2(q1.y, B[7].y, fma2(q1.x, B[6].y,
                        fma2(q0.y, B[5].y, mul2(q0.x, B[4].y))));

        uint64_t olo = abs2(mul2(p12a, p34a));   // (out0, out1)
        uint64_t ohi = abs2(mul2(p12b, p34b));   // (out2, out3)
        stg_cs_128(orow + (size_t)i * NS, olo, ohi);
    }
}

extern "C" void kernel_launch(void* const* d_in, const int* in_sizes, int n_in,
                              void* d_out, int out_size) {
    const float* x  = (const float*)d_in[0];
    const float* sv = (const float*)d_in[1];
    float* out = (float*)d_out;

    dim3 grid(NS / 256, NB / 64);   // 16 x 64 = 1024 blocks
    qk_pair_kernel<<<grid, 256>>>(x, sv, out);
}

// round 10
// speedup vs baseline: 1.3075x; 1.3075x over previous
#include <cuda_runtime.h>
#include <cuda_bf16.h>
#include <cstdint>

// out[b,s] = | prod_k cos((x[b,k]-sv[s,k])/2) |  =  | P12 * P34 |
// P12 = 1/2 [ cos((u+ - v+)/2) + cos((u- - v-)/2) ],  u± = x0±x1, v± = s0±s1
// each cos((u-v)/2) = cos(u/2)cos(v/2) + sin(u/2)sin(v/2)
// -> each P is a 4-term dot product of row features vs col features (1/2
//    folded into the row side).
// A records stored UN-duplicated (8 floats/row); lanes duplicate into packed
// f32x2 operands via mov.b64 (ALU) to cut LDS wavefronts (the top pipe).
#define NB 4096
#define NS 4096

__device__ __forceinline__ uint64_t mul2(uint64_t a, uint64_t b) {
    uint64_t r; asm("mul.rn.f32x2 %0, %1, %2;" : "=l"(r) : "l"(a), "l"(b)); return r;
}
__device__ __forceinline__ uint64_t fma2(uint64_t a, uint64_t b, uint64_t c) {
    uint64_t r; asm("fma.rn.f32x2 %0, %1, %2, %3;" : "=l"(r) : "l"(a), "l"(b), "l"(c)); return r;
}
__device__ __forceinline__ uint64_t abs2(uint64_t v) {
    asm("and.b64 %0, %0, 0x7FFFFFFF7FFFFFFF;" : "+l"(v)); return v;
}
__device__ __forceinline__ uint64_t dup2(float v) {
    uint64_t r; asm("mov.b64 %0, {%1, %1};" : "=l"(r) : "f"(v)); return r;
}

// Block: 64 rows x 256 cols. Thread: 4 cols x 16 rows. 4 blocks/SM.
__global__ __launch_bounds__(256, 4) void qk_pair_kernel(
    const float* __restrict__ x,
    const float* __restrict__ sv,
    float* __restrict__ out)
{
    // A (row) features, un-dup'd: per row 8 floats
    // {c+12, s+12, c-12, s-12, c+34, s+34, c-34, s-34}, 1/2 folded in.
    __shared__ __align__(16) float sxf[64 * 8];    // 2 KB
    // B (col) features f-major: {C+12,S+12,C-12,S-12,C+34,S+34,C-34,S-34}
    __shared__ __align__(16) float sbf[8 * 256];   // 8 KB

    const int b0 = blockIdx.y << 6;    // 64 rows
    const int s0 = blockIdx.x << 8;    // 256 cols
    const int t  = threadIdx.x;

    // ---- A fill: one sincos/thread (t = row*4 + g) ----
    {
        const int g = t & 3;
        float v = x[b0 * 4 + t];                       // coalesced
        float p = __shfl_xor_sync(0xFFFFFFFFu, v, 1);  // pair partner
        float u = (g & 1) ? (p - v) : (v + p);         // even: sum, odd: diff
        float sn, cs;
        __sincosf(u * 0.5f, &sn, &cs);
        cs *= 0.5f; sn *= 0.5f;                        // fold the 1/2 per pair
        // record slot: [row][2g] = cos, [row][2g+1] = sin
        sxf[((t >> 2) << 3) + (g << 1) + 0] = cs;
        sxf[((t >> 2) << 3) + (g << 1) + 1] = sn;
    }
    // ---- B fill: one col per thread, 4 sincos ----
    {
        float4 v = *reinterpret_cast<const float4*>(&sv[(size_t)(s0 + t) * 4]);
        float sn, cs;
        __sincosf((v.x + v.y) * 0.5f, &sn, &cs); sbf[0*256 + t] = cs; sbf[1*256 + t] = sn;
        __sincosf((v.x - v.y) * 0.5f, &sn, &cs); sbf[2*256 + t] = cs; sbf[3*256 + t] = sn;
        __sincosf((v.z + v.w) * 0.5f, &sn, &cs); sbf[4*256 + t] = cs; sbf[5*256 + t] = sn;
        __sincosf((v.z - v.w) * 0.5f, &sn, &cs); sbf[6*256 + t] = cs; sbf[7*256 + t] = sn;
    }
    __syncthreads();

    const int cg = t & 63;   // 4 cols starting at s0 + 4*cg
    const int rg = t >> 6;   // 16 rows starting at b0 + 16*rg (warp-uniform)

    // ---- hoist B features: 8 coalesced LDS.128 (32 regs, persistent) ----
    ulonglong2 B[8];
#pragma unroll
    for (int f = 0; f < 8; f++)
        B[f] = *reinterpret_cast<const ulonglong2*>(&sbf[f * 256 + (cg << 2)]);

    float* orow = out + (size_t)(b0 + (rg << 4)) * NS + (s0 + (cg << 2));

#pragma unroll 4
    for (int i = 0; i < 16; i++) {
        // 2 warp-broadcast LDS.128 per row (was 4 with dup'd records)
        const float4* arec = reinterpret_cast<const float4*>(
            &sxf[(((rg << 4) + i) << 3)]);
        float4 h0 = arec[0];   // c+12, s+12, c-12, s-12
        float4 h1 = arec[1];   // c+34, s+34, c-34, s-34

        // duplicate on ALU pipe (8 mov.b64 per row)
        uint64_t cp = dup2(h0.x), sp = dup2(h0.y);
        uint64_t cm = dup2(h0.z), sm = dup2(h0.w);

        uint64_t p12a = fma2(sm, B[3].x, fma2(cm, B[2].x,
                        fma2(sp, B[1].x, mul2(cp, B[0].x))));
        uint64_t p12b = fma2(sm, B[3].y, fma2(cm, B[2].y,
                        fma2(sp, B[1].y, mul2(cp, B[0].y))));

        cp = dup2(h1.x); sp = dup2(h1.y);
        cm = dup2(h1.z); sm = dup2(h1.w);

        uint64_t p34a = fma2(sm, B[7].x, fma2(cm, B[6].x,
                        fma2(sp, B[5].x, mul2(cp, B[4].x))));
        uint64_t p34b = fma2(sm, B[7].y, fma2(cm, B[6].y,
                        fma2(sp, B[5].y, mul2(cp, B[4].y))));

        ulonglong2 o;
        o.x = abs2(mul2(p12a, p34a));   // (out0, out1)
        o.y = abs2(mul2(p12b, p34b));   // (out2, out3)
        *reinterpret_cast<ulonglong2*>(orow + (size_t)i * NS) = o;  // STG.128
    }
}

extern "C" void kernel_launch(void* const* d_in, const int* in_sizes, int n_in,
                              void* d_out, int out_size) {
    const float* x  = (const float*)d_in[0];
    const float* sv = (const float*)d_in[1];
    float* out = (float*)d_out;

    dim3 grid(NS / 256, NB / 64);   // 16 x 64 = 1024 blocks
    qk_pair_kernel<<<grid, 256>>>(x, sv, out);
}